// round 2
// baseline (speedup 1.0000x reference)
#include <cuda_runtime.h>
#include <math.h>

// Problem shape (fixed by the dataset): B=64 batches, V=100000 verts, F=200000 faces.
#define BV 64
#define VN 100000
#define FN 200000
#define XN (VN * 3)       // 300000 "columns" (v*3+c) in the transpose view
#define CAP 64            // max neighbors per vertex (deg ~ 2*Poisson(6); P(>64) ~ 1e-13)

// ---- scratch (static __device__ globals — no runtime allocation) ----
__device__ float  g_vt[(size_t)XN * BV];   // transposed verts: [x = v*3+c][b]  (76.8 MB)
__device__ int    g_adj[(size_t)VN * CAP]; // capped adjacency (25.6 MB)
__device__ int    g_deg[VN];               // degree / fill cursor
__device__ double g_acc;                   // loss accumulator
__device__ int    g_is64;                  // faces dtype flag (1 = int64, 0 = int32)

// 0) detect faces dtype on-device (jax x64-disabled silently makes int64 -> int32)
__global__ void k_detect(const void* __restrict__ faces) {
    const long long* p64 = (const long long*)faces;
    int ok64 = 1;
#pragma unroll
    for (int t = 0; t < 16; t++) {
        long long v = p64[t];
        if (v < 0 || v >= VN) { ok64 = 0; break; }
    }
    g_is64 = ok64;
}

// 1) zero degree counters + accumulator
__global__ void k_zero() {
    int i = blockIdx.x * blockDim.x + threadIdx.x;
    if (i < VN) g_deg[i] = 0;
    if (i == 0) g_acc = 0.0;
}

// 2) build adjacency with multiplicity (matches reference edge list:
//    src=[i,j,j,k,k,i], dst=[j,i,k,j,i,k] -> i gets {j,k}, j gets {i,k}, k gets {j,i})
__global__ void k_build(const void* __restrict__ facesv) {
    int f = blockIdx.x * blockDim.x + threadIdx.x;
    if (f >= FN) return;
    int i, j, k;
    if (g_is64) {
        const long long* p = (const long long*)facesv;
        i = (int)p[3 * f + 0]; j = (int)p[3 * f + 1]; k = (int)p[3 * f + 2];
    } else {
        const int* p = (const int*)facesv;
        i = p[3 * f + 0]; j = p[3 * f + 1]; k = p[3 * f + 2];
    }
    // defensive clamp — never corrupt memory even on a wrong dtype guess
    if ((unsigned)i >= VN || (unsigned)j >= VN || (unsigned)k >= VN) return;
    int s;
    s = atomicAdd(&g_deg[i], 2);
    if (s     < CAP) g_adj[(size_t)i * CAP + s]     = j;
    if (s + 1 < CAP) g_adj[(size_t)i * CAP + s + 1] = k;
    s = atomicAdd(&g_deg[j], 2);
    if (s     < CAP) g_adj[(size_t)j * CAP + s]     = i;
    if (s + 1 < CAP) g_adj[(size_t)j * CAP + s + 1] = k;
    s = atomicAdd(&g_deg[k], 2);
    if (s     < CAP) g_adj[(size_t)k * CAP + s]     = j;
    if (s + 1 < CAP) g_adj[(size_t)k * CAP + s + 1] = i;
}

// 3) transpose verts [B][X] -> g_vt [X][B] via 32x32 smem tiles (both sides coalesced)
__global__ void k_transpose(const float* __restrict__ in) {
    __shared__ float tile[32][33];
    int x0 = blockIdx.x * 32;
    int b0 = blockIdx.y * 32;
    int tx = threadIdx.x, ty = threadIdx.y;   // blockDim (32, 8)
#pragma unroll
    for (int j = 0; j < 32; j += 8)
        tile[ty + j][tx] = in[(size_t)(b0 + ty + j) * XN + (x0 + tx)];
    __syncthreads();
#pragma unroll
    for (int j = 0; j < 32; j += 8)
        g_vt[(size_t)(x0 + ty + j) * BV + (b0 + tx)] = tile[tx][ty + j];
}

// 4) gather + loss. blockDim = (64, 4): lane group = batch, threadIdx.y = vertex slot.
//    Adjacency reads are uniform across the 64 batch-threads (L1 broadcast);
//    neighbor component reads are 128B-coalesced per warp.
__global__ void k_gather() {
    int b = threadIdx.x;                              // 0..63 (batch)
    int v = blockIdx.x * blockDim.y + threadIdx.y;    // vertex

    int d  = g_deg[v];
    int dc = min(d, CAP);
    const int* __restrict__ ap = &g_adj[(size_t)v * CAP];

    float a0 = 0.f, a1 = 0.f, a2 = 0.f;
#pragma unroll 4
    for (int s = 0; s < dc; s++) {
        int n = __ldg(&ap[s]);
        size_t base = (size_t)n * 3 * BV + b;
        a0 += __ldg(&g_vt[base]);
        a1 += __ldg(&g_vt[base + BV]);
        a2 += __ldg(&g_vt[base + 2 * BV]);
    }

    float inv = 1.0f / (float)max(d, 1);
    size_t ob = (size_t)v * 3 * BV + b;
    float l0 = g_vt[ob]          - a0 * inv;
    float l1 = g_vt[ob + BV]     - a1 * inv;
    float l2 = g_vt[ob + 2 * BV] - a2 * inv;
    float val = sqrtf(l0 * l0 + l1 * l1 + l2 * l2);

    // block reduction (256 threads) then one double atomic per block
    __shared__ float sh[256];
    int t = threadIdx.y * 64 + b;
    sh[t] = val;
    __syncthreads();
#pragma unroll
    for (int off = 128; off > 0; off >>= 1) {
        if (t < off) sh[t] += sh[t + off];
        __syncthreads();
    }
    if (t == 0) atomicAdd(&g_acc, (double)sh[0]);
}

// 5) finalize scalar mean
__global__ void k_final(float* __restrict__ out) {
    out[0] = (float)(g_acc / ((double)BV * (double)VN));
}

extern "C" void kernel_launch(void* const* d_in, const int* in_sizes, int n_in,
                              void* d_out, int out_size) {
    const float* verts = (const float*)d_in[0];
    const void*  faces = (const void*)d_in[1];
    // robust to input-order: faces tensor has exactly 3*F elements (either dtype),
    // verts has B*V*3 = 19.2M elements
    if (n_in >= 2 && in_sizes[0] == 3 * FN && in_sizes[1] != 3 * FN) {
        faces = (const void*)d_in[0];
        verts = (const float*)d_in[1];
    }

    k_detect<<<1, 1>>>(faces);
    k_zero<<<(VN + 255) / 256, 256>>>();
    k_build<<<(FN + 255) / 256, 256>>>(faces);
    k_transpose<<<dim3(XN / 32, BV / 32), dim3(32, 8)>>>(verts);
    k_gather<<<VN / 4, dim3(64, 4)>>>();
    k_final<<<1, 1>>>((float*)d_out);
}

// round 6
// speedup vs baseline: 1.5716x; 1.5716x over previous
#include <cuda_runtime.h>
#include <cuda_fp16.h>
#include <math.h>

// Problem shape (fixed by the dataset): B=64 batches, V=100000 verts, F=200000 faces.
#define BV 64
#define VN 100000
#define FN 200000
#define XN (VN * 3)       // 300000 rows (x = v*3+c) in the transposed view
#define CAP 64            // max neighbors per vertex (deg ~ 2*Poisson(6); P(>64) ~ 1e-13)

// ---- scratch (static __device__ globals — no runtime allocation) ----
__device__ __half2 g_vt2[(size_t)XN * (BV / 2)]; // transposed verts fp16: [x][b/2] (38.4 MB)
__device__ int     g_adj[(size_t)VN * CAP];      // capped adjacency (25.6 MB)
__device__ int     g_deg[VN];                    // degree / fill cursor
__device__ double  g_acc;                        // loss accumulator
__device__ int     g_is64;                       // faces dtype flag (1 = int64, 0 = int32)

// 0) detect faces dtype on-device (jax x64-disabled silently makes int64 -> int32)
__global__ void k_detect(const void* __restrict__ faces) {
    const long long* p64 = (const long long*)faces;
    int ok64 = 1;
#pragma unroll
    for (int t = 0; t < 16; t++) {
        long long v = p64[t];
        if (v < 0 || v >= VN) { ok64 = 0; break; }
    }
    g_is64 = ok64;
}

// 1) zero degree counters + accumulator
__global__ void k_zero() {
    int i = blockIdx.x * blockDim.x + threadIdx.x;
    if (i < VN) g_deg[i] = 0;
    if (i == 0) g_acc = 0.0;
}

// 2) build adjacency with multiplicity (reference edge list:
//    src=[i,j,j,k,k,i], dst=[j,i,k,j,i,k] -> i gets {j,k}, j gets {i,k}, k gets {j,i})
__global__ void k_build(const void* __restrict__ facesv) {
    int f = blockIdx.x * blockDim.x + threadIdx.x;
    if (f >= FN) return;
    int i, j, k;
    if (g_is64) {
        const long long* p = (const long long*)facesv;
        i = (int)p[3 * f + 0]; j = (int)p[3 * f + 1]; k = (int)p[3 * f + 2];
    } else {
        const int* p = (const int*)facesv;
        i = p[3 * f + 0]; j = p[3 * f + 1]; k = p[3 * f + 2];
    }
    if ((unsigned)i >= VN || (unsigned)j >= VN || (unsigned)k >= VN) return;
    int s;
    s = atomicAdd(&g_deg[i], 2);
    if (s     < CAP) g_adj[(size_t)i * CAP + s]     = j;
    if (s + 1 < CAP) g_adj[(size_t)i * CAP + s + 1] = k;
    s = atomicAdd(&g_deg[j], 2);
    if (s     < CAP) g_adj[(size_t)j * CAP + s]     = i;
    if (s + 1 < CAP) g_adj[(size_t)j * CAP + s + 1] = k;
    s = atomicAdd(&g_deg[k], 2);
    if (s     < CAP) g_adj[(size_t)k * CAP + s]     = j;
    if (s + 1 < CAP) g_adj[(size_t)k * CAP + s + 1] = i;
}

// 3) transpose+convert verts [B=64][X] fp32 -> g_vt2 [X][B/2] fp16x2.
//    Block tile: 32 x-rows × 64 b-cols. blockDim (32, 8).
//    Read: 128B coalesced fp32 rows; write: 128B coalesced half2 rows.
//    Tile row stride = 66 floats (EVEN) so the float2 LDS below is 8B-aligned
//    and conflict-free (lane tx covers banks {2tx, 2tx+1}: a permutation).
__global__ void k_transpose(const float* __restrict__ in) {
    __shared__ float tile[32][66];            // [x_local][b]
    int x0 = blockIdx.x * 32;
    int tx = threadIdx.x, ty = threadIdx.y;
#pragma unroll
    for (int j = 0; j < 8; j++) {             // 64 b-rows, 8 at a time
        int bl = ty + 8 * j;
        tile[tx][bl] = in[(size_t)bl * XN + (x0 + tx)];
    }
    __syncthreads();
#pragma unroll
    for (int j = 0; j < 4; j++) {             // 32 x-rows, 8 at a time
        int xl = ty + 8 * j;
        float2 v2 = *(const float2*)&tile[xl][2 * tx];   // aligned LDS.64
        g_vt2[(size_t)(x0 + xl) * 32 + tx] = __floats2half2_rn(v2.x, v2.y);
    }
}

// 4) gather + loss. blockDim (32, 8): lane = batch pair (half2), ty = vertex slot.
//    One warp per vertex -> adjacency loop is uniform (no divergence),
//    every neighbor row load is 32 lanes x 4B = 128B coalesced.
__global__ void k_gather() {
    int tx = threadIdx.x;                          // 0..31, handles batches 2tx, 2tx+1
    int v  = blockIdx.x * 8 + threadIdx.y;

    int d  = g_deg[v];
    int dc = min(d, CAP);
    const int* __restrict__ ap = &g_adj[(size_t)v * CAP];

    float a0x = 0.f, a0y = 0.f, a1x = 0.f, a1y = 0.f, a2x = 0.f, a2y = 0.f;
#pragma unroll 4
    for (int s = 0; s < dc; s++) {
        int n = __ldg(&ap[s]);                     // uniform -> broadcast
        size_t base = (size_t)n * 96 + tx;         // n*3*(BV/2) + lane
        float2 x0 = __half22float2(__ldg(&g_vt2[base]));
        float2 x1 = __half22float2(__ldg(&g_vt2[base + 32]));
        float2 x2 = __half22float2(__ldg(&g_vt2[base + 64]));
        a0x += x0.x; a0y += x0.y;
        a1x += x1.x; a1y += x1.y;
        a2x += x2.x; a2y += x2.y;
    }

    float inv = 1.0f / (float)max(d, 1);
    size_t ob = (size_t)v * 96 + tx;
    float2 c0 = __half22float2(__ldg(&g_vt2[ob]));
    float2 c1 = __half22float2(__ldg(&g_vt2[ob + 32]));
    float2 c2 = __half22float2(__ldg(&g_vt2[ob + 64]));

    float l0 = c0.x - a0x * inv, l1 = c1.x - a1x * inv, l2 = c2.x - a2x * inv;
    float m0 = c0.y - a0y * inv, m1 = c1.y - a1y * inv, m2 = c2.y - a2y * inv;
    float val = sqrtf(l0 * l0 + l1 * l1 + l2 * l2)
              + sqrtf(m0 * m0 + m1 * m1 + m2 * m2);

    // block reduction (256 threads) then one double atomic per block
    __shared__ float sh[256];
    int t = threadIdx.y * 32 + tx;
    sh[t] = val;
    __syncthreads();
#pragma unroll
    for (int off = 128; off > 0; off >>= 1) {
        if (t < off) sh[t] += sh[t + off];
        __syncthreads();
    }
    if (t == 0) atomicAdd(&g_acc, (double)sh[0]);
}

// 5) finalize scalar mean
__global__ void k_final(float* __restrict__ out) {
    out[0] = (float)(g_acc / ((double)BV * (double)VN));
}

extern "C" void kernel_launch(void* const* d_in, const int* in_sizes, int n_in,
                              void* d_out, int out_size) {
    const float* verts = (const float*)d_in[0];
    const void*  faces = (const void*)d_in[1];
    if (n_in >= 2 && in_sizes[0] == 3 * FN && in_sizes[1] != 3 * FN) {
        faces = (const void*)d_in[0];
        verts = (const float*)d_in[1];
    }

    k_detect<<<1, 1>>>(faces);
    k_zero<<<(VN + 255) / 256, 256>>>();
    k_build<<<(FN + 255) / 256, 256>>>(faces);
    k_transpose<<<XN / 32, dim3(32, 8)>>>(verts);
    k_gather<<<VN / 8, dim3(32, 8)>>>();
    k_final<<<1, 1>>>((float*)d_out);
}